// round 3
// baseline (speedup 1.0000x reference)
#include <cuda_runtime.h>
#include <math.h>
#include <stdint.h>

constexpr int B = 64, L = 20, H = 300, P = 8;
constexpr int NN = 32768, EE = 262144, CC = 2048, OUTD = 1845, STEPS = 3;
constexpr int H4 = 4 * H, H2 = 2 * H, CE = CC + 1;
constexpr int NPG = NN / B;     // 512
constexpr int NI = STEPS + 1;   // 4
constexpr int NODE_SHIFT = 9, EDGE_SHIFT = 12;

constexpr size_t ALIGNF(size_t x) { return (x + 15) & ~size_t(15); }
constexpr size_t OFF_QT    = 0;
constexpr size_t OFF_SIM   = ALIGNF(OFF_QT + (size_t)B * L * H);
constexpr size_t OFF_TAG   = ALIGNF(OFF_SIM + (size_t)B * L * CE);
constexpr size_t OFF_XPRE  = ALIGNF(OFF_TAG + (size_t)B * L * H);
constexpr size_t OFF_ENC   = ALIGNF(OFF_XPRE + (size_t)B * L * H4);
constexpr size_t OFF_EPRE  = ALIGNF(OFF_ENC + (size_t)B * H);
constexpr size_t OFF_HID   = ALIGNF(OFF_EPRE + (size_t)B * H);
constexpr size_t OFF_INSTR = ALIGNF(OFF_HID + (size_t)B * NI * H);
constexpr size_t OFF_NPS   = ALIGNF(OFF_INSTR + (size_t)B * NI * H);
constexpr size_t OFF_RSIM  = ALIGNF(OFF_NPS + (size_t)B * P);
constexpr size_t OFF_SCALEA= ALIGNF(OFF_RSIM + (size_t)B);
constexpr size_t OFF_NSRAW = ALIGNF(OFF_SCALEA + (size_t)B * P * H);
constexpr size_t OFF_NRRAW = OFF_NSRAW + (size_t)NN;
constexpr size_t OFF_ESRAW = OFF_NRRAW + (size_t)NN;
constexpr size_t OFF_DIST  = ALIGNF(OFF_ESRAW + (size_t)EE);
constexpr size_t OFF_AGG   = ALIGNF(OFF_DIST + (size_t)NN);
constexpr size_t OFF_FEAT  = ALIGNF(OFF_AGG + (size_t)B * H);
constexpr size_t OFF_HID1  = ALIGNF(OFF_FEAT + (size_t)B * H2);
constexpr size_t TOTALF    = ALIGNF(OFF_HID1 + (size_t)B * H2);

__device__ float g_scratch[TOTALF];

__device__ __forceinline__ float sigf(float x) { return 1.0f / (1.0f + __expf(-x)); }
__device__ __forceinline__ float eluf(float x) { return x > 0.0f ? x : expm1f(x); }

__global__ void zero_kernel(float* __restrict__ p, int n) {
    int i = blockIdx.x * blockDim.x + threadIdx.x;
    if (i < n) p[i] = 0.0f;
}
__global__ void init_dist_kernel(float* __restrict__ p) {
    int i = blockIdx.x * blockDim.x + threadIdx.x;
    if (i < NN) p[i] = 1.0f / (float)NPG;
}

// C(MxN) = A(MxK) @ B(KxN) [+bias][elu], row-major
__global__ __launch_bounds__(256) void sgemm_nn(
    const float* __restrict__ A, int lda, const float* __restrict__ Bm, int ldb,
    float* __restrict__ Cm, int ldc, int M, int K, int N,
    const float* __restrict__ bias1, const float* __restrict__ bias2, int act) {
    __shared__ float As[16][68];
    __shared__ float Bs[16][64];
    int tid = threadIdx.x, tx = tid & 15, ty = tid >> 4;
    int m0 = blockIdx.x * 64, n0 = blockIdx.y * 64;
    float acc[4][4] = {};
    int lr = tid >> 2, lk = (tid & 3) * 4, bk = tid >> 4, bn = tid & 15;
    for (int k0 = 0; k0 < K; k0 += 16) {
#pragma unroll
        for (int j = 0; j < 4; j++) {
            int kk = lk + j, gm = m0 + lr, gk = k0 + kk;
            As[kk][lr] = (gm < M && gk < K) ? A[(size_t)gm * lda + gk] : 0.0f;
        }
#pragma unroll
        for (int j = 0; j < 4; j++) {
            int n = bn + j * 16, gk = k0 + bk, gn = n0 + n;
            Bs[bk][n] = (gk < K && gn < N) ? Bm[(size_t)gk * ldb + gn] : 0.0f;
        }
        __syncthreads();
#pragma unroll
        for (int kk = 0; kk < 16; kk++) {
            float a0 = As[kk][ty*4+0], a1 = As[kk][ty*4+1], a2 = As[kk][ty*4+2], a3 = As[kk][ty*4+3];
#pragma unroll
            for (int j = 0; j < 4; j++) {
                float bv = Bs[kk][tx + j * 16];
                acc[0][j] += a0*bv; acc[1][j] += a1*bv; acc[2][j] += a2*bv; acc[3][j] += a3*bv;
            }
        }
        __syncthreads();
    }
#pragma unroll
    for (int i = 0; i < 4; i++) {
        int gm = m0 + ty * 4 + i; if (gm >= M) continue;
#pragma unroll
        for (int j = 0; j < 4; j++) {
            int gn = n0 + tx + j * 16; if (gn >= N) continue;
            float v = acc[i][j];
            if (bias1) v += bias1[gn];
            if (bias2) v += bias2[gn];
            if (act) v = eluf(v);
            Cm[(size_t)gm * ldc + gn] = v;
        }
    }
}

// C(MxN) = A(MxK) @ B(NxK)^T [+bias][elu]
__global__ __launch_bounds__(256) void sgemm_nt(
    const float* __restrict__ A, int lda, const float* __restrict__ Bm, int ldb,
    float* __restrict__ Cm, int ldc, int M, int K, int N,
    const float* __restrict__ bias1, const float* __restrict__ bias2, int act) {
    __shared__ float As[16][68];
    __shared__ float Bs[16][68];
    int tid = threadIdx.x, tx = tid & 15, ty = tid >> 4;
    int m0 = blockIdx.x * 64, n0 = blockIdx.y * 64;
    float acc[4][4] = {};
    int lr = tid >> 2, lk = (tid & 3) * 4;
    for (int k0 = 0; k0 < K; k0 += 16) {
#pragma unroll
        for (int j = 0; j < 4; j++) {
            int kk = lk + j, gm = m0 + lr, gk = k0 + kk;
            As[kk][lr] = (gm < M && gk < K) ? A[(size_t)gm * lda + gk] : 0.0f;
        }
#pragma unroll
        for (int j = 0; j < 4; j++) {
            int kk = lk + j, gn = n0 + lr, gk = k0 + kk;
            Bs[kk][lr] = (gn < N && gk < K) ? Bm[(size_t)gn * ldb + gk] : 0.0f;
        }
        __syncthreads();
#pragma unroll
        for (int kk = 0; kk < 16; kk++) {
            float a0 = As[kk][ty*4+0], a1 = As[kk][ty*4+1], a2 = As[kk][ty*4+2], a3 = As[kk][ty*4+3];
#pragma unroll
            for (int j = 0; j < 4; j++) {
                float bv = Bs[kk][tx + j * 16];
                acc[0][j] += a0*bv; acc[1][j] += a1*bv; acc[2][j] += a2*bv; acc[3][j] += a3*bv;
            }
        }
        __syncthreads();
    }
#pragma unroll
    for (int i = 0; i < 4; i++) {
        int gm = m0 + ty * 4 + i; if (gm >= M) continue;
#pragma unroll
        for (int j = 0; j < 4; j++) {
            int gn = n0 + tx + j * 16; if (gn >= N) continue;
            float v = acc[i][j];
            if (bias1) v += bias1[gn];
            if (bias2) v += bias2[gn];
            if (act) v = eluf(v);
            Cm[(size_t)gm * ldc + gn] = v;
        }
    }
}

// out[m] += sum_n elu( sum_k A[m,k]*scale[b(m),k]*W[k,n] ) * wvec[n]; b(m)=m>>bshift
__global__ __launch_bounds__(256) void fused_gemm(
    const float* __restrict__ A, int lda,
    const float* __restrict__ scale, int sstride, int bshift,
    const float* __restrict__ W, int NW, const float* __restrict__ wvec,
    float* __restrict__ outv, int M, int K) {
    __shared__ float As[16][68];
    __shared__ float Ws[16][160];
    int tid = threadIdx.x, tx = tid & 15, ty = tid >> 4;
    int m0 = blockIdx.x * 64, n0 = blockIdx.y * 160;
    const float* sc = scale + (size_t)(m0 >> bshift) * sstride;
    float acc[4][10] = {};
    int lr = tid >> 2, lk = (tid & 3) * 4, wk = tid >> 4, wn = tid & 15;
    for (int k0 = 0; k0 < K; k0 += 16) {
        if (k0 + 16 <= K) {
            float4 av = *reinterpret_cast<const float4*>(&A[(size_t)(m0 + lr) * lda + k0 + lk]);
            As[lk+0][lr] = av.x * sc[k0+lk+0];
            As[lk+1][lr] = av.y * sc[k0+lk+1];
            As[lk+2][lr] = av.z * sc[k0+lk+2];
            As[lk+3][lr] = av.w * sc[k0+lk+3];
        } else {
#pragma unroll
            for (int j = 0; j < 4; j++) {
                int gk = k0 + lk + j;
                As[lk+j][lr] = (gk < K) ? A[(size_t)(m0 + lr) * lda + gk] * sc[gk] : 0.0f;
            }
        }
#pragma unroll
        for (int j = 0; j < 10; j++) {
            int n = wn + j * 16, gk = k0 + wk, gn = n0 + n;
            Ws[wk][n] = (gk < K && gn < NW) ? W[(size_t)gk * NW + gn] : 0.0f;
        }
        __syncthreads();
#pragma unroll
        for (int kk = 0; kk < 16; kk++) {
            float a0 = As[kk][ty*4+0], a1 = As[kk][ty*4+1], a2 = As[kk][ty*4+2], a3 = As[kk][ty*4+3];
#pragma unroll
            for (int j = 0; j < 10; j++) {
                float bv = Ws[kk][tx + j * 16];
                acc[0][j] += a0*bv; acc[1][j] += a1*bv; acc[2][j] += a2*bv; acc[3][j] += a3*bv;
            }
        }
        __syncthreads();
    }
    float wv[10];
#pragma unroll
    for (int j = 0; j < 10; j++) {
        int gn = n0 + tx + j * 16;
        wv[j] = (gn < NW) ? wvec[gn] : 0.0f;
    }
#pragma unroll
    for (int i = 0; i < 4; i++) {
        float part = 0.0f;
#pragma unroll
        for (int j = 0; j < 10; j++) part += eluf(acc[i][j]) * wv[j];
#pragma unroll
        for (int off = 8; off > 0; off >>= 1)
            part += __shfl_down_sync(0xffffffffu, part, off, 16);
        if (tx == 0) atomicAdd(&outv[m0 + ty * 4 + i], part);
    }
}

__global__ void tag_softmax_kernel(const float* __restrict__ qt,
                                   const float* __restrict__ defemb,
                                   float* __restrict__ sim) {
    int r = blockIdx.x, tid = threadIdx.x;
    __shared__ float red[256];
    float d = 0.0f;
    for (int k = tid; k < H; k += 256) d += qt[(size_t)r * H + k] * defemb[k];
    red[tid] = d; __syncthreads();
    for (int s = 128; s > 0; s >>= 1) { if (tid < s) red[tid] += red[tid+s]; __syncthreads(); }
    float* row = &sim[(size_t)r * CE];
    if (tid == 0) row[CC] = red[0];
    __syncthreads();
    float mx = -1e30f;
    for (int c = tid; c < CE; c += 256) mx = fmaxf(mx, row[c]);
    red[tid] = mx; __syncthreads();
    for (int s = 128; s > 0; s >>= 1) { if (tid < s) red[tid] = fmaxf(red[tid], red[tid+s]); __syncthreads(); }
    mx = red[0]; __syncthreads();
    float sum = 0.0f;
    for (int c = tid; c < CE; c += 256) { float e = __expf(row[c] - mx); row[c] = e; sum += e; }
    red[tid] = sum; __syncthreads();
    for (int s = 128; s > 0; s >>= 1) { if (tid < s) red[tid] += red[tid+s]; __syncthreads(); }
    float inv = 1.0f / red[0];
    for (int c = tid; c < CE; c += 256) row[c] *= inv;
}

__global__ void addq_kernel(const float* __restrict__ q, const float* __restrict__ sim,
                            float* __restrict__ tag) {
    int idx = blockIdx.x * blockDim.x + threadIdx.x;
    if (idx < B * L * H) {
        int r = idx / H;
        tag[idx] += sim[(size_t)r * CE + CC] * q[idx];
    }
}

__global__ void lstm_kernel(const float* __restrict__ xpre, const float* __restrict__ Whh,
                            float* __restrict__ enc) {
    int b = blockIdx.x, tid = threadIdx.x;
    __shared__ float hs[H], cs[H];
    if (tid < H) { hs[tid] = 0.0f; cs[tid] = 0.0f; }
    for (int t = 0; t < L; t++) {
        __syncthreads();
        float zi = 0, zf = 0, zg = 0, zo = 0;
        if (tid < H) {
            const float* xp = &xpre[((size_t)b * L + t) * H4];
            zi = xp[tid]; zf = xp[H+tid]; zg = xp[2*H+tid]; zo = xp[3*H+tid];
            const float* wi = &Whh[(size_t)tid * H];
            const float* wf = &Whh[(size_t)(H + tid) * H];
            const float* wg = &Whh[(size_t)(2*H + tid) * H];
            const float* wo = &Whh[(size_t)(3*H + tid) * H];
            for (int k = 0; k < H; k++) {
                float hv = hs[k];
                zi += wi[k]*hv; zf += wf[k]*hv; zg += wg[k]*hv; zo += wo[k]*hv;
            }
        }
        __syncthreads();
        if (tid < H) {
            float c = sigf(zf) * cs[tid] + sigf(zi) * tanhf(zg);
            cs[tid] = c;
            hs[tid] = sigf(zo) * tanhf(c);
        }
    }
    __syncthreads();
    if (tid < H) enc[(size_t)b * H + tid] = hs[tid];
}

__global__ void rnn_kernel(const float* __restrict__ epre, const float* __restrict__ Whh,
                           float* __restrict__ hidden) {
    int b = blockIdx.x, tid = threadIdx.x;
    __shared__ float hx[H];
    if (tid < H) hx[tid] = 0.0f;
    for (int s = 0; s < NI; s++) {
        __syncthreads();
        float z = 0.0f;
        if (tid < H) {
            z = epre[(size_t)b * H + tid];
            const float* w = &Whh[(size_t)tid * H];
            for (int k = 0; k < H; k++) z += w[k] * hx[k];
            z = fmaxf(z, 0.0f);
        }
        __syncthreads();
        if (tid < H) {
            hx[tid] = z;
            hidden[((size_t)b * NI + s) * H + tid] = z;
        }
    }
}

__global__ void attn_kernel(const float* __restrict__ hidden, const float* __restrict__ tagged,
                            float* __restrict__ instr) {
    int bi = blockIdx.x, b = bi / NI;
    const float* hv = &hidden[(size_t)bi * H];
    __shared__ float sc[L];
    int warp = threadIdx.x >> 5, lane = threadIdx.x & 31;
    for (int q = 0; q < 5; q++) {
        int l = warp * 5 + q;
        float s = 0.0f;
        for (int k = lane; k < H; k += 32) s += hv[k] * tagged[((size_t)b * L + l) * H + k];
        for (int off = 16; off > 0; off >>= 1) s += __shfl_down_sync(0xffffffffu, s, off);
        if (lane == 0) sc[l] = s;
    }
    __syncthreads();
    if (threadIdx.x == 0) {
        float mx = sc[0];
        for (int l = 1; l < L; l++) mx = fmaxf(mx, sc[l]);
        float sum = 0.0f;
        for (int l = 0; l < L; l++) { float e = __expf(sc[l] - mx); sc[l] = e; sum += e; }
        float inv = 1.0f / sum;
        for (int l = 0; l < L; l++) sc[l] *= inv;
    }
    __syncthreads();
    for (int h = threadIdx.x; h < H; h += blockDim.x) {
        float v = 0.0f;
        for (int l = 0; l < L; l++) v += sc[l] * tagged[((size_t)b * L + l) * H + h];
        instr[(size_t)bi * H + h] = v;
    }
}

__global__ void psim_kernel(const float* __restrict__ instr, int s,
                            const float* __restrict__ pe,
                            float* __restrict__ npsim, float* __restrict__ rsim,
                            float* __restrict__ scaleA) {
    int b = blockIdx.x, tid = threadIdx.x;
    const float* iv = &instr[((size_t)b * NI + s) * H];
    __shared__ float sc[P + 1];
    __shared__ float ps[P + 1];
    int warp = tid >> 5, lane = tid & 31;
    if (warp < P + 1) {
        float v = 0.0f;
        for (int k = lane; k < H; k += 32) v += iv[k] * pe[(size_t)warp * H + k];
        for (int off = 16; off > 0; off >>= 1) v += __shfl_down_sync(0xffffffffu, v, off);
        if (lane == 0) sc[warp] = v;
    }
    __syncthreads();
    if (tid == 0) {
        float mx = sc[0];
        for (int q = 1; q <= P; q++) mx = fmaxf(mx, sc[q]);
        float sum = 0.0f;
        for (int q = 0; q <= P; q++) { float e = __expf(sc[q] - mx); ps[q] = e; sum += e; }
        float inv = 1.0f / sum;
        for (int q = 0; q <= P; q++) ps[q] *= inv;
        rsim[b] = ps[P];
        for (int p = 0; p < P; p++) npsim[(size_t)b * P + p] = ps[p];
    }
    __syncthreads();
    for (int idx = tid; idx < P * H; idx += blockDim.x) {
        int p = idx / H, h = idx - p * H;
        scaleA[(size_t)b * (P * H) + idx] = ps[p] * iv[h];
    }
}

__global__ void scatter_kernel(const float* __restrict__ es, const int* __restrict__ src,
                               const int* __restrict__ dst, const float* __restrict__ dist,
                               float* __restrict__ nr) {
    int e = blockIdx.x * blockDim.x + threadIdx.x;
    if (e < EE) atomicAdd(&nr[dst[e]], dist[src[e]] * es[e]);
}

__global__ void seg_kernel(const float* __restrict__ ns_raw, const float* __restrict__ nr_raw,
                           const float* __restrict__ rsim, float* __restrict__ dist) {
    int b = blockIdx.x, tid = threadIdx.x;
    int n = b * NPG + tid;
    float a = ns_raw[n], r = nr_raw[n];
    __shared__ float red[NPG];
    red[tid] = a; __syncthreads();
    for (int s = NPG/2; s > 0; s >>= 1) { if (tid < s) red[tid] = fmaxf(red[tid], red[tid+s]); __syncthreads(); }
    float ma = red[0]; __syncthreads();
    float ea = __expf(a - ma);
    red[tid] = ea; __syncthreads();
    for (int s = NPG/2; s > 0; s >>= 1) { if (tid < s) red[tid] += red[tid+s]; __syncthreads(); }
    float sa = red[0]; __syncthreads();
    red[tid] = r; __syncthreads();
    for (int s = NPG/2; s > 0; s >>= 1) { if (tid < s) red[tid] = fmaxf(red[tid], red[tid+s]); __syncthreads(); }
    float mr = red[0]; __syncthreads();
    float er = __expf(r - mr);
    red[tid] = er; __syncthreads();
    for (int s = NPG/2; s > 0; s >>= 1) { if (tid < s) red[tid] += red[tid+s]; __syncthreads(); }
    float sr = red[0];
    float rs = rsim[b];
    dist[n] = rs * (er / sr) + (1.0f - rs) * (ea / sa);
}

__global__ void agg_kernel(const float* __restrict__ attrs, const float* __restrict__ npsim,
                           const float* __restrict__ dist, float* __restrict__ agg) {
    int b = blockIdx.x, chunk = blockIdx.y, tid = threadIdx.x;
    __shared__ float np[P];
    __shared__ float dw[64];
    if (tid < P) np[tid] = npsim[(size_t)b * P + tid];
    int n0 = b * NPG + chunk * 64;
    if (tid < 64) dw[tid] = dist[n0 + tid];
    __syncthreads();
    if (tid < H) {
        float acc = 0.0f;
        for (int q = 0; q < 64; q++) {
            const float* ar = &attrs[(size_t)(n0 + q) * P * H];
            float s = 0.0f;
#pragma unroll
            for (int p = 0; p < P; p++) s += np[p] * ar[(size_t)p * H + tid];
            acc += dw[q] * s;
        }
        atomicAdd(&agg[(size_t)b * H + tid], acc);
    }
}

__global__ void concat_kernel(const float* __restrict__ enc, const float* __restrict__ agg,
                              float* __restrict__ feat) {
    int idx = blockIdx.x * blockDim.x + threadIdx.x;
    if (idx < B * H2) {
        int b = idx / H2, h = idx % H2;
        feat[idx] = (h < H) ? enc[(size_t)b * H + h] : agg[(size_t)b * H + h - H];
    }
}

static inline dim3 g2(int M, int N) { return dim3((M + 63) / 64, (N + 63) / 64); }

extern "C" void kernel_launch(void* const* d_in, const int* in_sizes, int n_in,
                              void* d_out, int out_size) {
    const float* questions = (const float*)d_in[0];
    const float* vocab     = (const float*)d_in[1];
    const float* pe        = (const float*)d_in[2];
    const float* attrs     = (const float*)d_in[3];
    const float* eattrs    = (const float*)d_in[4];
    const float* w_tag     = (const float*)d_in[5];
    const float* defemb    = (const float*)d_in[6];
    const float* lWih      = (const float*)d_in[7];
    const float* lWhh      = (const float*)d_in[8];
    const float* lbih      = (const float*)d_in[9];
    const float* lbhh      = (const float*)d_in[10];
    const float* rWih      = (const float*)d_in[11];
    const float* rWhh      = (const float*)d_in[12];
    const float* rbih      = (const float*)d_in[13];
    const float* rbhh      = (const float*)d_in[14];
    const float* Wp        = (const float*)d_in[15];
    const float* We        = (const float*)d_in[16];
    const float* w_ns      = (const float*)d_in[17];
    const float* w_rs      = (const float*)d_in[18];
    const float* fc1_w     = (const float*)d_in[19];
    const float* fc1_b     = (const float*)d_in[20];
    const float* fc2_w     = (const float*)d_in[21];
    const float* fc2_b     = (const float*)d_in[22];
    const int*   esrc      = (const int*)d_in[24];
    const int*   edst      = (const int*)d_in[25];
    float* out = (float*)d_out;

    float* S = nullptr;
    cudaGetSymbolAddress((void**)&S, g_scratch);
    float* QT = S + OFF_QT;     float* SIM = S + OFF_SIM;   float* TAG = S + OFF_TAG;
    float* XPRE = S + OFF_XPRE; float* ENC = S + OFF_ENC;   float* EPRE = S + OFF_EPRE;
    float* HID = S + OFF_HID;   float* INSTR = S + OFF_INSTR;
    float* NPS = S + OFF_NPS;   float* RSIM = S + OFF_RSIM; float* SCALEA = S + OFF_SCALEA;
    float* NSRAW = S + OFF_NSRAW; float* NRRAW = S + OFF_NRRAW; float* ESRAW = S + OFF_ESRAW;
    float* DIST = S + OFF_DIST; float* AGG = S + OFF_AGG;
    float* FEAT = S + OFF_FEAT; float* HID1 = S + OFF_HID1;

    int BL = B * L;
    sgemm_nn<<<g2(BL, H), 256>>>(questions, H, w_tag, H, QT, H, BL, H, H, nullptr, nullptr, 0);
    sgemm_nt<<<g2(BL, CC), 256>>>(QT, H, vocab, H, SIM, CE, BL, H, CC, nullptr, nullptr, 0);
    tag_softmax_kernel<<<BL, 256>>>(QT, defemb, SIM);
    sgemm_nn<<<g2(BL, H), 256>>>(SIM, CE, vocab, H, TAG, H, BL, CC, H, nullptr, nullptr, 0);
    addq_kernel<<<(BL * H + 255) / 256, 256>>>(questions, SIM, TAG);
    sgemm_nt<<<g2(BL, H4), 256>>>(TAG, H, lWih, H, XPRE, H4, BL, H, H4, lbih, lbhh, 0);
    lstm_kernel<<<B, 320>>>(XPRE, lWhh, ENC);
    sgemm_nt<<<g2(B, H), 256>>>(ENC, H, rWih, H, EPRE, H, B, H, H, rbih, rbhh, 0);
    rnn_kernel<<<B, 320>>>(EPRE, rWhh, HID);
    attn_kernel<<<B * NI, 128>>>(HID, TAG, INSTR);
    init_dist_kernel<<<(NN + 255) / 256, 256>>>(DIST);
    for (int step = 0; step < STEPS; step++) {
        zero_kernel<<<(2 * NN + EE + 255) / 256, 256>>>(NSRAW, 2 * NN + EE);
        psim_kernel<<<B, 320>>>(INSTR, step, pe, NPS, RSIM, SCALEA);
        fused_gemm<<<dim3(NN / 64, 2), 256>>>(attrs, P * H, SCALEA, P * H, NODE_SHIFT,
                                              Wp, H, w_ns, NSRAW, NN, P * H);
        fused_gemm<<<dim3(EE / 64, 2), 256>>>(eattrs, H, INSTR + (size_t)step * H, NI * H,
                                              EDGE_SHIFT, We, H, w_rs, ESRAW, EE, H);
        scatter_kernel<<<EE / 256, 256>>>(ESRAW, esrc, edst, DIST, NRRAW);
        seg_kernel<<<B, NPG>>>(NSRAW, NRRAW, RSIM, DIST);
    }
    psim_kernel<<<B, 320>>>(INSTR, STEPS, pe, NPS, RSIM, SCALEA);
    zero_kernel<<<(B * H + 255) / 256, 256>>>(AGG, B * H);
    agg_kernel<<<dim3(B, NPG / 64), 320>>>(attrs, NPS, DIST, AGG);
    concat_kernel<<<(B * H2 + 255) / 256, 256>>>(ENC, AGG, FEAT);
    sgemm_nt<<<g2(B, H2), 256>>>(FEAT, H2, fc1_w, H2, HID1, H2, B, H2, H2, fc1_b, nullptr, 1);
    sgemm_nt<<<g2(B, OUTD), 256>>>(HID1, H2, fc2_w, H2, out, OUTD, B, H2, OUTD, fc2_b, nullptr, 0);
}

// round 4
// speedup vs baseline: 1.2174x; 1.2174x over previous
#include <cuda_runtime.h>
#include <math.h>
#include <stdint.h>

constexpr int B = 64, L = 20, H = 300, P = 8;
constexpr int NN = 32768, EE = 262144, CC = 2048, OUTD = 1845, STEPS = 3;
constexpr int H4 = 4 * H, H2 = 2 * H, CE = CC + 1;
constexpr int NPG = NN / B;     // 512
constexpr int NI = STEPS + 1;   // 4
constexpr int NODE_SHIFT = 9, EDGE_SHIFT = 12;

constexpr size_t ALIGNF(size_t x) { return (x + 15) & ~size_t(15); }
constexpr size_t OFF_QT    = 0;
constexpr size_t OFF_SIM   = ALIGNF(OFF_QT + (size_t)B * L * H);
constexpr size_t OFF_TAG   = ALIGNF(OFF_SIM + (size_t)B * L * CE);
constexpr size_t OFF_XPRE  = ALIGNF(OFF_TAG + (size_t)B * L * H);
constexpr size_t OFF_ENC   = ALIGNF(OFF_XPRE + (size_t)B * L * H4);
constexpr size_t OFF_EPRE  = ALIGNF(OFF_ENC + (size_t)B * H);
constexpr size_t OFF_HID   = ALIGNF(OFF_EPRE + (size_t)B * H);
constexpr size_t OFF_INSTR = ALIGNF(OFF_HID + (size_t)B * NI * H);
constexpr size_t OFF_NPS   = ALIGNF(OFF_INSTR + (size_t)B * NI * H);
constexpr size_t OFF_RSIM  = ALIGNF(OFF_NPS + (size_t)B * P);
constexpr size_t OFF_SCALEA= ALIGNF(OFF_RSIM + (size_t)B);
constexpr size_t OFF_NSRAW = ALIGNF(OFF_SCALEA + (size_t)B * P * H);
constexpr size_t OFF_NRRAW = OFF_NSRAW + (size_t)NN;
constexpr size_t OFF_ESRAW = OFF_NRRAW + (size_t)NN;
constexpr size_t OFF_DIST  = ALIGNF(OFF_ESRAW + (size_t)EE);
constexpr size_t OFF_AGG   = ALIGNF(OFF_DIST + (size_t)NN);
constexpr size_t OFF_FEAT  = ALIGNF(OFF_AGG + (size_t)B * H);
constexpr size_t OFF_HID1  = ALIGNF(OFF_FEAT + (size_t)B * H2);
constexpr size_t TOTALF    = ALIGNF(OFF_HID1 + (size_t)B * H2);

__device__ float g_scratch[TOTALF];

__device__ __forceinline__ float sigf(float x) { return 1.0f / (1.0f + __expf(-x)); }
__device__ __forceinline__ float eluf(float x) { return x > 0.0f ? x : expm1f(x); }

// packed f32x2 helpers (Blackwell FFMA2 — only reachable via PTX)
#define FMA_F32X2(d, a, b) \
    asm("fma.rn.f32x2 %0, %1, %2, %0;" : "+l"(d) : "l"(a), "l"(b))
#define PACK_F32X2(out, lo, hi) \
    asm("mov.b64 %0, {%1, %2};" : "=l"(out) : "f"(lo), "f"(hi))
#define UNPACK_F32X2(lo, hi, in) \
    asm("mov.b64 {%0, %1}, %2;" : "=f"(lo), "=f"(hi) : "l"(in))

__global__ void zero_kernel(float* __restrict__ p, int n) {
    int i = blockIdx.x * blockDim.x + threadIdx.x;
    if (i < n) p[i] = 0.0f;
}
__global__ void init_dist_kernel(float* __restrict__ p) {
    int i = blockIdx.x * blockDim.x + threadIdx.x;
    if (i < NN) p[i] = 1.0f / (float)NPG;
}

// C(MxN) = A(MxK) @ B(KxN) [+bias][elu], row-major
__global__ __launch_bounds__(256) void sgemm_nn(
    const float* __restrict__ A, int lda, const float* __restrict__ Bm, int ldb,
    float* __restrict__ Cm, int ldc, int M, int K, int N,
    const float* __restrict__ bias1, const float* __restrict__ bias2, int act) {
    __shared__ float As[16][68];
    __shared__ float Bs[16][64];
    int tid = threadIdx.x, tx = tid & 15, ty = tid >> 4;
    int m0 = blockIdx.x * 64, n0 = blockIdx.y * 64;
    unsigned long long acc[4][2] = {};
    int lr = tid >> 2, lk = (tid & 3) * 4, bk = tid >> 4, bn = tid & 15;
    for (int k0 = 0; k0 < K; k0 += 16) {
#pragma unroll
        for (int j = 0; j < 4; j++) {
            int kk = lk + j, gm = m0 + lr, gk = k0 + kk;
            As[kk][lr] = (gm < M && gk < K) ? A[(size_t)gm * lda + gk] : 0.0f;
        }
#pragma unroll
        for (int j = 0; j < 4; j++) {
            int n = bn + j * 16, gk = k0 + bk, gn = n0 + n;
            Bs[bk][n] = (gk < K && gn < N) ? Bm[(size_t)gk * ldb + gn] : 0.0f;
        }
        __syncthreads();
#pragma unroll
        for (int kk = 0; kk < 16; kk++) {
            float4 av = *reinterpret_cast<const float4*>(&As[kk][ty * 4]);
            unsigned long long pa0, pa1, pa2, pa3;
            PACK_F32X2(pa0, av.x, av.x); PACK_F32X2(pa1, av.y, av.y);
            PACK_F32X2(pa2, av.z, av.z); PACK_F32X2(pa3, av.w, av.w);
#pragma unroll
            for (int j = 0; j < 2; j++) {
                unsigned long long bv =
                    *reinterpret_cast<const unsigned long long*>(&Bs[kk][2 * tx + j * 32]);
                FMA_F32X2(acc[0][j], pa0, bv);
                FMA_F32X2(acc[1][j], pa1, bv);
                FMA_F32X2(acc[2][j], pa2, bv);
                FMA_F32X2(acc[3][j], pa3, bv);
            }
        }
        __syncthreads();
    }
#pragma unroll
    for (int i = 0; i < 4; i++) {
        int gm = m0 + ty * 4 + i; if (gm >= M) continue;
#pragma unroll
        for (int j = 0; j < 2; j++) {
            float lo, hi;
            UNPACK_F32X2(lo, hi, acc[i][j]);
            int gn = n0 + 2 * tx + j * 32;
#pragma unroll
            for (int half = 0; half < 2; half++) {
                int g = gn + half; if (g >= N) continue;
                float v = half ? hi : lo;
                if (bias1) v += bias1[g];
                if (bias2) v += bias2[g];
                if (act) v = eluf(v);
                Cm[(size_t)gm * ldc + g] = v;
            }
        }
    }
}

// C(MxN) = A(MxK) @ B(NxK)^T [+bias][elu]
__global__ __launch_bounds__(256) void sgemm_nt(
    const float* __restrict__ A, int lda, const float* __restrict__ Bm, int ldb,
    float* __restrict__ Cm, int ldc, int M, int K, int N,
    const float* __restrict__ bias1, const float* __restrict__ bias2, int act) {
    __shared__ float As[16][68];
    __shared__ float Bs[16][68];
    int tid = threadIdx.x, tx = tid & 15, ty = tid >> 4;
    int m0 = blockIdx.x * 64, n0 = blockIdx.y * 64;
    unsigned long long acc[4][2] = {};
    int lr = tid >> 2, lk = (tid & 3) * 4;
    for (int k0 = 0; k0 < K; k0 += 16) {
#pragma unroll
        for (int j = 0; j < 4; j++) {
            int kk = lk + j, gm = m0 + lr, gk = k0 + kk;
            As[kk][lr] = (gm < M && gk < K) ? A[(size_t)gm * lda + gk] : 0.0f;
        }
#pragma unroll
        for (int j = 0; j < 4; j++) {
            int kk = lk + j, gn = n0 + lr, gk = k0 + kk;
            Bs[kk][lr] = (gn < N && gk < K) ? Bm[(size_t)gn * ldb + gk] : 0.0f;
        }
        __syncthreads();
#pragma unroll
        for (int kk = 0; kk < 16; kk++) {
            float4 av = *reinterpret_cast<const float4*>(&As[kk][ty * 4]);
            unsigned long long pa0, pa1, pa2, pa3;
            PACK_F32X2(pa0, av.x, av.x); PACK_F32X2(pa1, av.y, av.y);
            PACK_F32X2(pa2, av.z, av.z); PACK_F32X2(pa3, av.w, av.w);
#pragma unroll
            for (int j = 0; j < 2; j++) {
                unsigned long long bv =
                    *reinterpret_cast<const unsigned long long*>(&Bs[kk][2 * tx + j * 32]);
                FMA_F32X2(acc[0][j], pa0, bv);
                FMA_F32X2(acc[1][j], pa1, bv);
                FMA_F32X2(acc[2][j], pa2, bv);
                FMA_F32X2(acc[3][j], pa3, bv);
            }
        }
        __syncthreads();
    }
#pragma unroll
    for (int i = 0; i < 4; i++) {
        int gm = m0 + ty * 4 + i; if (gm >= M) continue;
#pragma unroll
        for (int j = 0; j < 2; j++) {
            float lo, hi;
            UNPACK_F32X2(lo, hi, acc[i][j]);
            int gn = n0 + 2 * tx + j * 32;
#pragma unroll
            for (int half = 0; half < 2; half++) {
                int g = gn + half; if (g >= N) continue;
                float v = half ? hi : lo;
                if (bias1) v += bias1[g];
                if (bias2) v += bias2[g];
                if (act) v = eluf(v);
                Cm[(size_t)gm * ldc + g] = v;
            }
        }
    }
}

// out[m] += sum_n elu( sum_k A[m,k]*scale[b(m),k]*W[k,n] ) * wvec[n]; b(m)=m>>bshift
__global__ __launch_bounds__(256) void fused_gemm(
    const float* __restrict__ A, int lda,
    const float* __restrict__ scale, int sstride, int bshift,
    const float* __restrict__ W, int NW, const float* __restrict__ wvec,
    float* __restrict__ outv, int M, int K) {
    __shared__ float As[16][68];
    __shared__ float Ws[16][160];
    int tid = threadIdx.x, tx = tid & 15, ty = tid >> 4;
    int m0 = blockIdx.x * 64, n0 = blockIdx.y * 160;
    const float* sc = scale + (size_t)(m0 >> bshift) * sstride;
    unsigned long long acc[4][5] = {};
    int lr = tid >> 2, lk = (tid & 3) * 4, wk = tid >> 4, wn = tid & 15;
    for (int k0 = 0; k0 < K; k0 += 16) {
        if (k0 + 16 <= K) {
            float4 av = *reinterpret_cast<const float4*>(&A[(size_t)(m0 + lr) * lda + k0 + lk]);
            As[lk+0][lr] = av.x * sc[k0+lk+0];
            As[lk+1][lr] = av.y * sc[k0+lk+1];
            As[lk+2][lr] = av.z * sc[k0+lk+2];
            As[lk+3][lr] = av.w * sc[k0+lk+3];
        } else {
#pragma unroll
            for (int j = 0; j < 4; j++) {
                int gk = k0 + lk + j;
                As[lk+j][lr] = (gk < K) ? A[(size_t)(m0 + lr) * lda + gk] * sc[gk] : 0.0f;
            }
        }
#pragma unroll
        for (int j = 0; j < 10; j++) {
            int n = wn + j * 16, gk = k0 + wk, gn = n0 + n;
            Ws[wk][n] = (gk < K && gn < NW) ? W[(size_t)gk * NW + gn] : 0.0f;
        }
        __syncthreads();
#pragma unroll
        for (int kk = 0; kk < 16; kk++) {
            float4 av = *reinterpret_cast<const float4*>(&As[kk][ty * 4]);
            unsigned long long pa0, pa1, pa2, pa3;
            PACK_F32X2(pa0, av.x, av.x); PACK_F32X2(pa1, av.y, av.y);
            PACK_F32X2(pa2, av.z, av.z); PACK_F32X2(pa3, av.w, av.w);
#pragma unroll
            for (int j = 0; j < 5; j++) {
                unsigned long long bv =
                    *reinterpret_cast<const unsigned long long*>(&Ws[kk][2 * tx + j * 32]);
                FMA_F32X2(acc[0][j], pa0, bv);
                FMA_F32X2(acc[1][j], pa1, bv);
                FMA_F32X2(acc[2][j], pa2, bv);
                FMA_F32X2(acc[3][j], pa3, bv);
            }
        }
        __syncthreads();
    }
    float wlo[5], whi[5];
#pragma unroll
    for (int j = 0; j < 5; j++) {
        int gn = n0 + 2 * tx + j * 32;
        wlo[j] = (gn < NW) ? wvec[gn] : 0.0f;
        whi[j] = (gn + 1 < NW) ? wvec[gn + 1] : 0.0f;
    }
#pragma unroll
    for (int i = 0; i < 4; i++) {
        float part = 0.0f;
#pragma unroll
        for (int j = 0; j < 5; j++) {
            float lo, hi;
            UNPACK_F32X2(lo, hi, acc[i][j]);
            part += eluf(lo) * wlo[j] + eluf(hi) * whi[j];
        }
#pragma unroll
        for (int off = 8; off > 0; off >>= 1)
            part += __shfl_down_sync(0xffffffffu, part, off, 16);
        if (tx == 0) atomicAdd(&outv[m0 + ty * 4 + i], part);
    }
}

__global__ void tag_softmax_kernel(const float* __restrict__ qt,
                                   const float* __restrict__ defemb,
                                   float* __restrict__ sim) {
    int r = blockIdx.x, tid = threadIdx.x;
    __shared__ float red[256];
    float d = 0.0f;
    for (int k = tid; k < H; k += 256) d += qt[(size_t)r * H + k] * defemb[k];
    red[tid] = d; __syncthreads();
    for (int s = 128; s > 0; s >>= 1) { if (tid < s) red[tid] += red[tid+s]; __syncthreads(); }
    float* row = &sim[(size_t)r * CE];
    if (tid == 0) row[CC] = red[0];
    __syncthreads();
    float mx = -1e30f;
    for (int c = tid; c < CE; c += 256) mx = fmaxf(mx, row[c]);
    red[tid] = mx; __syncthreads();
    for (int s = 128; s > 0; s >>= 1) { if (tid < s) red[tid] = fmaxf(red[tid], red[tid+s]); __syncthreads(); }
    mx = red[0]; __syncthreads();
    float sum = 0.0f;
    for (int c = tid; c < CE; c += 256) { float e = __expf(row[c] - mx); row[c] = e; sum += e; }
    red[tid] = sum; __syncthreads();
    for (int s = 128; s > 0; s >>= 1) { if (tid < s) red[tid] += red[tid+s]; __syncthreads(); }
    float inv = 1.0f / red[0];
    for (int c = tid; c < CE; c += 256) row[c] *= inv;
}

__global__ void addq_kernel(const float* __restrict__ q, const float* __restrict__ sim,
                            float* __restrict__ tag) {
    int idx = blockIdx.x * blockDim.x + threadIdx.x;
    if (idx < B * L * H) {
        int r = idx / H;
        tag[idx] += sim[(size_t)r * CE + CC] * q[idx];
    }
}

__global__ void lstm_kernel(const float* __restrict__ xpre, const float* __restrict__ Whh,
                            float* __restrict__ enc) {
    int b = blockIdx.x, tid = threadIdx.x;
    __shared__ float hs[H], cs[H];
    if (tid < H) { hs[tid] = 0.0f; cs[tid] = 0.0f; }
    for (int t = 0; t < L; t++) {
        __syncthreads();
        float zi = 0, zf = 0, zg = 0, zo = 0;
        if (tid < H) {
            const float* xp = &xpre[((size_t)b * L + t) * H4];
            zi = xp[tid]; zf = xp[H+tid]; zg = xp[2*H+tid]; zo = xp[3*H+tid];
            const float* wi = &Whh[(size_t)tid * H];
            const float* wf = &Whh[(size_t)(H + tid) * H];
            const float* wg = &Whh[(size_t)(2*H + tid) * H];
            const float* wo = &Whh[(size_t)(3*H + tid) * H];
            for (int k = 0; k < H; k++) {
                float hv = hs[k];
                zi += wi[k]*hv; zf += wf[k]*hv; zg += wg[k]*hv; zo += wo[k]*hv;
            }
        }
        __syncthreads();
        if (tid < H) {
            float c = sigf(zf) * cs[tid] + sigf(zi) * tanhf(zg);
            cs[tid] = c;
            hs[tid] = sigf(zo) * tanhf(c);
        }
    }
    __syncthreads();
    if (tid < H) enc[(size_t)b * H + tid] = hs[tid];
}

__global__ void rnn_kernel(const float* __restrict__ epre, const float* __restrict__ Whh,
                           float* __restrict__ hidden) {
    int b = blockIdx.x, tid = threadIdx.x;
    __shared__ float hx[H];
    if (tid < H) hx[tid] = 0.0f;
    for (int s = 0; s < NI; s++) {
        __syncthreads();
        float z = 0.0f;
        if (tid < H) {
            z = epre[(size_t)b * H + tid];
            const float* w = &Whh[(size_t)tid * H];
            for (int k = 0; k < H; k++) z += w[k] * hx[k];
            z = fmaxf(z, 0.0f);
        }
        __syncthreads();
        if (tid < H) {
            hx[tid] = z;
            hidden[((size_t)b * NI + s) * H + tid] = z;
        }
    }
}

__global__ void attn_kernel(const float* __restrict__ hidden, const float* __restrict__ tagged,
                            float* __restrict__ instr) {
    int bi = blockIdx.x, b = bi / NI;
    const float* hv = &hidden[(size_t)bi * H];
    __shared__ float sc[L];
    int warp = threadIdx.x >> 5, lane = threadIdx.x & 31;
    for (int q = 0; q < 5; q++) {
        int l = warp * 5 + q;
        float s = 0.0f;
        for (int k = lane; k < H; k += 32) s += hv[k] * tagged[((size_t)b * L + l) * H + k];
        for (int off = 16; off > 0; off >>= 1) s += __shfl_down_sync(0xffffffffu, s, off);
        if (lane == 0) sc[l] = s;
    }
    __syncthreads();
    if (threadIdx.x == 0) {
        float mx = sc[0];
        for (int l = 1; l < L; l++) mx = fmaxf(mx, sc[l]);
        float sum = 0.0f;
        for (int l = 0; l < L; l++) { float e = __expf(sc[l] - mx); sc[l] = e; sum += e; }
        float inv = 1.0f / sum;
        for (int l = 0; l < L; l++) sc[l] *= inv;
    }
    __syncthreads();
    for (int h = threadIdx.x; h < H; h += blockDim.x) {
        float v = 0.0f;
        for (int l = 0; l < L; l++) v += sc[l] * tagged[((size_t)b * L + l) * H + h];
        instr[(size_t)bi * H + h] = v;
    }
}

__global__ void psim_kernel(const float* __restrict__ instr, int s,
                            const float* __restrict__ pe,
                            float* __restrict__ npsim, float* __restrict__ rsim,
                            float* __restrict__ scaleA) {
    int b = blockIdx.x, tid = threadIdx.x;
    const float* iv = &instr[((size_t)b * NI + s) * H];
    __shared__ float sc[P + 1];
    __shared__ float ps[P + 1];
    int warp = tid >> 5, lane = tid & 31;
    if (warp < P + 1) {
        float v = 0.0f;
        for (int k = lane; k < H; k += 32) v += iv[k] * pe[(size_t)warp * H + k];
        for (int off = 16; off > 0; off >>= 1) v += __shfl_down_sync(0xffffffffu, v, off);
        if (lane == 0) sc[warp] = v;
    }
    __syncthreads();
    if (tid == 0) {
        float mx = sc[0];
        for (int q = 1; q <= P; q++) mx = fmaxf(mx, sc[q]);
        float sum = 0.0f;
        for (int q = 0; q <= P; q++) { float e = __expf(sc[q] - mx); ps[q] = e; sum += e; }
        float inv = 1.0f / sum;
        for (int q = 0; q <= P; q++) ps[q] *= inv;
        rsim[b] = ps[P];
        for (int p = 0; p < P; p++) npsim[(size_t)b * P + p] = ps[p];
    }
    __syncthreads();
    for (int idx = tid; idx < P * H; idx += blockDim.x) {
        int p = idx / H, h = idx - p * H;
        scaleA[(size_t)b * (P * H) + idx] = ps[p] * iv[h];
    }
}

__global__ void scatter_kernel(const float* __restrict__ es, const int* __restrict__ src,
                               const int* __restrict__ dst, const float* __restrict__ dist,
                               float* __restrict__ nr) {
    int e = blockIdx.x * blockDim.x + threadIdx.x;
    if (e < EE) atomicAdd(&nr[dst[e]], dist[src[e]] * es[e]);
}

__global__ void seg_kernel(const float* __restrict__ ns_raw, const float* __restrict__ nr_raw,
                           const float* __restrict__ rsim, float* __restrict__ dist) {
    int b = blockIdx.x, tid = threadIdx.x;
    int n = b * NPG + tid;
    float a = ns_raw[n], r = nr_raw[n];
    __shared__ float red[NPG];
    red[tid] = a; __syncthreads();
    for (int s = NPG/2; s > 0; s >>= 1) { if (tid < s) red[tid] = fmaxf(red[tid], red[tid+s]); __syncthreads(); }
    float ma = red[0]; __syncthreads();
    float ea = __expf(a - ma);
    red[tid] = ea; __syncthreads();
    for (int s = NPG/2; s > 0; s >>= 1) { if (tid < s) red[tid] += red[tid+s]; __syncthreads(); }
    float sa = red[0]; __syncthreads();
    red[tid] = r; __syncthreads();
    for (int s = NPG/2; s > 0; s >>= 1) { if (tid < s) red[tid] = fmaxf(red[tid], red[tid+s]); __syncthreads(); }
    float mr = red[0]; __syncthreads();
    float er = __expf(r - mr);
    red[tid] = er; __syncthreads();
    for (int s = NPG/2; s > 0; s >>= 1) { if (tid < s) red[tid] += red[tid+s]; __syncthreads(); }
    float sr = red[0];
    float rs = rsim[b];
    dist[n] = rs * (er / sr) + (1.0f - rs) * (ea / sa);
}

__global__ void agg_kernel(const float* __restrict__ attrs, const float* __restrict__ npsim,
                           const float* __restrict__ dist, float* __restrict__ agg) {
    int b = blockIdx.x, chunk = blockIdx.y, tid = threadIdx.x;
    __shared__ float np[P];
    __shared__ float dw[64];
    if (tid < P) np[tid] = npsim[(size_t)b * P + tid];
    int n0 = b * NPG + chunk * 64;
    if (tid < 64) dw[tid] = dist[n0 + tid];
    __syncthreads();
    if (tid < H) {
        float acc = 0.0f;
        for (int q = 0; q < 64; q++) {
            const float* ar = &attrs[(size_t)(n0 + q) * P * H];
            float s = 0.0f;
#pragma unroll
            for (int p = 0; p < P; p++) s += np[p] * ar[(size_t)p * H + tid];
            acc += dw[q] * s;
        }
        atomicAdd(&agg[(size_t)b * H + tid], acc);
    }
}

__global__ void concat_kernel(const float* __restrict__ enc, const float* __restrict__ agg,
                              float* __restrict__ feat) {
    int idx = blockIdx.x * blockDim.x + threadIdx.x;
    if (idx < B * H2) {
        int b = idx / H2, h = idx % H2;
        feat[idx] = (h < H) ? enc[(size_t)b * H + h] : agg[(size_t)b * H + h - H];
    }
}

static inline dim3 g2(int M, int N) { return dim3((M + 63) / 64, (N + 63) / 64); }

extern "C" void kernel_launch(void* const* d_in, const int* in_sizes, int n_in,
                              void* d_out, int out_size) {
    const float* questions = (const float*)d_in[0];
    const float* vocab     = (const float*)d_in[1];
    const float* pe        = (const float*)d_in[2];
    const float* attrs     = (const float*)d_in[3];
    const float* eattrs    = (const float*)d_in[4];
    const float* w_tag     = (const float*)d_in[5];
    const float* defemb    = (const float*)d_in[6];
    const float* lWih      = (const float*)d_in[7];
    const float* lWhh      = (const float*)d_in[8];
    const float* lbih      = (const float*)d_in[9];
    const float* lbhh      = (const float*)d_in[10];
    const float* rWih      = (const float*)d_in[11];
    const float* rWhh      = (const float*)d_in[12];
    const float* rbih      = (const float*)d_in[13];
    const float* rbhh      = (const float*)d_in[14];
    const float* Wp        = (const float*)d_in[15];
    const float* We        = (const float*)d_in[16];
    const float* w_ns      = (const float*)d_in[17];
    const float* w_rs      = (const float*)d_in[18];
    const float* fc1_w     = (const float*)d_in[19];
    const float* fc1_b     = (const float*)d_in[20];
    const float* fc2_w     = (const float*)d_in[21];
    const float* fc2_b     = (const float*)d_in[22];
    const int*   esrc      = (const int*)d_in[24];
    const int*   edst      = (const int*)d_in[25];
    float* out = (float*)d_out;

    float* S = nullptr;
    cudaGetSymbolAddress((void**)&S, g_scratch);
    float* QT = S + OFF_QT;     float* SIM = S + OFF_SIM;   float* TAG = S + OFF_TAG;
    float* XPRE = S + OFF_XPRE; float* ENC = S + OFF_ENC;   float* EPRE = S + OFF_EPRE;
    float* HID = S + OFF_HID;   float* INSTR = S + OFF_INSTR;
    float* NPS = S + OFF_NPS;   float* RSIM = S + OFF_RSIM; float* SCALEA = S + OFF_SCALEA;
    float* NSRAW = S + OFF_NSRAW; float* NRRAW = S + OFF_NRRAW; float* ESRAW = S + OFF_ESRAW;
    float* DIST = S + OFF_DIST; float* AGG = S + OFF_AGG;
    float* FEAT = S + OFF_FEAT; float* HID1 = S + OFF_HID1;

    int BL = B * L;
    sgemm_nn<<<g2(BL, H), 256>>>(questions, H, w_tag, H, QT, H, BL, H, H, nullptr, nullptr, 0);
    sgemm_nt<<<g2(BL, CC), 256>>>(QT, H, vocab, H, SIM, CE, BL, H, CC, nullptr, nullptr, 0);
    tag_softmax_kernel<<<BL, 256>>>(QT, defemb, SIM);
    sgemm_nn<<<g2(BL, H), 256>>>(SIM, CE, vocab, H, TAG, H, BL, CC, H, nullptr, nullptr, 0);
    addq_kernel<<<(BL * H + 255) / 256, 256>>>(questions, SIM, TAG);
    sgemm_nt<<<g2(BL, H4), 256>>>(TAG, H, lWih, H, XPRE, H4, BL, H, H4, lbih, lbhh, 0);
    lstm_kernel<<<B, 320>>>(XPRE, lWhh, ENC);
    sgemm_nt<<<g2(B, H), 256>>>(ENC, H, rWih, H, EPRE, H, B, H, H, rbih, rbhh, 0);
    rnn_kernel<<<B, 320>>>(EPRE, rWhh, HID);
    attn_kernel<<<B * NI, 128>>>(HID, TAG, INSTR);
    init_dist_kernel<<<(NN + 255) / 256, 256>>>(DIST);
    for (int step = 0; step < STEPS; step++) {
        zero_kernel<<<(2 * NN + EE + 255) / 256, 256>>>(NSRAW, 2 * NN + EE);
        psim_kernel<<<B, 320>>>(INSTR, step, pe, NPS, RSIM, SCALEA);
        fused_gemm<<<dim3(NN / 64, 2), 256>>>(attrs, P * H, SCALEA, P * H, NODE_SHIFT,
                                              Wp, H, w_ns, NSRAW, NN, P * H);
        fused_gemm<<<dim3(EE / 64, 2), 256>>>(eattrs, H, INSTR + (size_t)step * H, NI * H,
                                              EDGE_SHIFT, We, H, w_rs, ESRAW, EE, H);
        scatter_kernel<<<EE / 256, 256>>>(ESRAW, esrc, edst, DIST, NRRAW);
        seg_kernel<<<B, NPG>>>(NSRAW, NRRAW, RSIM, DIST);
    }
    psim_kernel<<<B, 320>>>(INSTR, STEPS, pe, NPS, RSIM, SCALEA);
    zero_kernel<<<(B * H + 255) / 256, 256>>>(AGG, B * H);
    agg_kernel<<<dim3(B, NPG / 64), 320>>>(attrs, NPS, DIST, AGG);
    concat_kernel<<<(B * H2 + 255) / 256, 256>>>(ENC, AGG, FEAT);
    sgemm_nt<<<g2(B, H2), 256>>>(FEAT, H2, fc1_w, H2, HID1, H2, B, H2, H2, fc1_b, nullptr, 1);
    sgemm_nt<<<g2(B, OUTD), 256>>>(HID1, H2, fc2_w, H2, out, OUTD, B, H2, OUTD, fc2_b, nullptr, 0);
}